// round 12
// baseline (speedup 1.0000x reference)
#include <cuda_runtime.h>
#include <cuda_fp16.h>

#define N_NODES 65536
#define N_EDGES 1048576
#define HID 80
#define SA_STRIDE 328   // padded 320 to reduce smem bank conflicts

typedef unsigned long long u64;

// ---------------- static scratch (no allocations allowed) ----------------
__device__ float g_h0[N_NODES * HID];        // h fp32 ping (21 MB)
__device__ float g_h1[N_NODES * HID];        // h fp32 pong (21 MB)
__device__ int   g_deg[N_NODES];             // zero at load; re-zeroed by k_scan each run
__device__ int   g_rowptr[N_NODES + 1];
__device__ int   g_cursor[N_NODES];
__device__ int   g_csrc[N_EDGES];
__device__ uint2 g_coefh[N_EDGES];           // 4 x fp16 coef (8 MB)

// e3nn fan-in norms * 1/sqrt(2) * 1/sqrt(DEG=16)
#define K1C (0.03125f)
#define K2C (0.025515518f)
#define K3C (0.03125f)
#define K4C (0.044194174f)

__device__ __forceinline__ unsigned int h2u(float a, float b) {
    __half2 h = __floats2half2_rn(a, b);
    return *(const unsigned int*)&h;
}
__device__ __forceinline__ uint2 pack4h(float a, float b, float c, float d) {
    uint2 r; r.x = h2u(a, b); r.y = h2u(c, d); return r;
}
__device__ __forceinline__ float4 unpack4h(uint2 p) {
    float2 lo = __half22float2(*(const __half2*)&p.x);
    float2 hi = __half22float2(*(const __half2*)&p.y);
    return make_float4(lo.x, lo.y, hi.x, hi.y);
}
__device__ __forceinline__ u64 packf2(float a, float b) {
    u64 r; asm("mov.b64 %0, {%1, %2};" : "=l"(r) : "f"(a), "f"(b)); return r;
}
__device__ __forceinline__ float2 unpackf2(u64 v) {
    float2 f; asm("mov.b64 {%0, %1}, %2;" : "=f"(f.x), "=f"(f.y) : "l"(v)); return f;
}
__device__ __forceinline__ void ffma2(u64& acc, u64 a, u64 b) {
    asm("fma.rn.f32x2 %0, %1, %2, %0;" : "+l"(acc) : "l"(a), "l"(b));
}

// ---------------- fused preprocessing: hist + input embed ----------------
__global__ void k_pre(const int* __restrict__ dst, int* __restrict__ deg,
                      const float* __restrict__ x, const float* __restrict__ W_in,
                      const float* __restrict__ b_in, float* __restrict__ h) {
    int b = blockIdx.x;
    if (b < N_EDGES / 256) {
        int e = b * 256 + threadIdx.x;
        atomicAdd(&deg[dst[e]], 1);
    } else {
        int id = (b - N_EDGES / 256) * 256 + threadIdx.x;   // < N*80
        int n = id / HID, c = id % HID;
        const float* xr = x + n * 16;
        float acc = b_in[c];
#pragma unroll
        for (int i = 0; i < 16; i++) acc = fmaf(xr[i], W_in[i * HID + c], acc);
        h[id] = acc;
    }
}

// single-block (1024 threads) exclusive scan over 65536 ints; re-zeroes deg (replay-safe)
__global__ __launch_bounds__(1024) void k_scan(
    int* __restrict__ deg, int* __restrict__ rowptr, int* __restrict__ cursor)
{
    __shared__ int wsum[32];
    int tid = threadIdx.x;
    int lane = tid & 31, wid = tid >> 5;
    int base = tid * 64;
    const int4* d4 = (const int4*)(deg + base);
    int s = 0;
#pragma unroll
    for (int i = 0; i < 16; i++) {
        int4 v = d4[i];
        s += v.x + v.y + v.z + v.w;
    }
    int v = s;
#pragma unroll
    for (int d = 1; d < 32; d <<= 1) {
        int t = __shfl_up_sync(0xffffffffu, v, d);
        if (lane >= d) v += t;
    }
    if (lane == 31) wsum[wid] = v;
    __syncthreads();
    if (wid == 0) {
        int w = wsum[lane];
        int wv = w;
#pragma unroll
        for (int d = 1; d < 32; d <<= 1) {
            int t = __shfl_up_sync(0xffffffffu, wv, d);
            if (lane >= d) wv += t;
        }
        wsum[lane] = wv - w;
    }
    __syncthreads();
    int off = wsum[wid] + (v - s);
#pragma unroll 4
    for (int i = 0; i < 16; i++) {
        int4 dv = d4[i];
        int b = base + 4 * i;
        rowptr[b + 0] = off; cursor[b + 0] = off; off += dv.x;
        rowptr[b + 1] = off; cursor[b + 1] = off; off += dv.y;
        rowptr[b + 2] = off; cursor[b + 2] = off; off += dv.z;
        rowptr[b + 3] = off; cursor[b + 3] = off; off += dv.w;
    }
    int4* d4w = (int4*)(deg + base);
    int4 z = make_int4(0, 0, 0, 0);
#pragma unroll 4
    for (int i = 0; i < 16; i++) d4w[i] = z;
    if (tid == 1023) rowptr[N_NODES] = off;
}

__global__ void k_csr(const int* __restrict__ src, const int* __restrict__ dst,
                      const float4* __restrict__ eattr,
                      int* __restrict__ cursor, int* __restrict__ csrc,
                      uint2* __restrict__ coefh) {
    int e = blockIdx.x * blockDim.x + threadIdx.x;
    if (e >= N_EDGES) return;
    int d = dst[e];
    int pos = atomicAdd(&cursor[d], 1);
    csrc[pos] = src[e];
    float4 cf = eattr[e];
    coefh[pos] = pack4h(cf.x, cf.y, cf.z, cf.w);   // (s2, v2x, v2y, v2z)
}

// ================= fused layer: aggregate (warp/node) + transform =================
// Reads hin, writes hout — DISJOINT buffers (ping-pong) to avoid cross-block races.

struct LayerSmem {
    float s_w1[1024], s_w2[512], s_w3[512], s_w4[256];
    float s_A[8][SA_STRIDE];
    int   s_src[8][32];
    u64   s_cf[8][32][4];
};

__device__ __forceinline__ void layer_agg(
    LayerSmem* sm, const ulonglong2* __restrict__ hq,
    const int* __restrict__ rowptr, const int* __restrict__ csrc,
    const uint2* __restrict__ coefh, int wid, int lane, int n)
{
    int beg = rowptr[n], end = rowptr[n + 1];
    u64 a0 = 0, a1 = 0, b0 = 0, b1 = 0, c0 = 0, c1 = 0, d0 = 0, d1 = 0;
    for (int base = beg; base < end; base += 32) {
        int cnt = min(32, end - base);
        __syncwarp();
        if (lane < cnt) {
            sm->s_src[wid][lane] = csrc[base + lane];
            float4 cf = unpack4h(coefh[base + lane]);
            sm->s_cf[wid][lane][0] = packf2(cf.x, cf.x);
            sm->s_cf[wid][lane][1] = packf2(cf.y, cf.y);
            sm->s_cf[wid][lane][2] = packf2(cf.z, cf.z);
            sm->s_cf[wid][lane][3] = packf2(cf.w, cf.w);
        }
        __syncwarp();
        if (lane < 20) {
#pragma unroll 4
            for (int i = 0; i < cnt; i++) {
                int s = sm->s_src[wid][i];
                ulonglong2 f = hq[s * 20 + lane];     // 4 floats, pre-paired
                const ulonglong2* cf2 = (const ulonglong2*)sm->s_cf[wid][i];
                ulonglong2 cab = cf2[0];              // (cx,cx), (cy,cy)
                ulonglong2 ccd = cf2[1];              // (cz,cz), (cw,cw)
                ffma2(a0, cab.x, f.x); ffma2(a1, cab.x, f.y);
                ffma2(b0, cab.y, f.x); ffma2(b1, cab.y, f.y);
                ffma2(c0, ccd.x, f.x); ffma2(c1, ccd.x, f.y);
                ffma2(d0, ccd.y, f.x); ffma2(d1, ccd.y, f.y);
            }
        }
    }
    if (lane < 20) {
        float* An = sm->s_A[wid];
        float2 p, q;
        p = unpackf2(a0); q = unpackf2(a1);
        *(float4*)&An[0   + 4 * lane] = make_float4(p.x, p.y, q.x, q.y);
        p = unpackf2(b0); q = unpackf2(b1);
        *(float4*)&An[80  + 4 * lane] = make_float4(p.x, p.y, q.x, q.y);
        p = unpackf2(c0); q = unpackf2(c1);
        *(float4*)&An[160 + 4 * lane] = make_float4(p.x, p.y, q.x, q.y);
        p = unpackf2(d0); q = unpackf2(d1);
        *(float4*)&An[240 + 4 * lane] = make_float4(p.x, p.y, q.x, q.y);
    }
}

__device__ __forceinline__ void stage_w(
    LayerSmem* sm, int tid, int nth,
    const float* __restrict__ w1, const float* __restrict__ w2,
    const float* __restrict__ w3, const float* __restrict__ w4)
{
    for (int i = tid; i < 1024; i += nth) sm->s_w1[i] = K1C * w1[i];
    for (int i = tid; i < 512;  i += nth) sm->s_w2[i] = K2C * w2[i];
    for (int i = tid; i < 512;  i += nth) sm->s_w3[i] = K3C * w3[i];
    for (int i = tid; i < 256;  i += nth) sm->s_w4[i] = K4C * w4[i];
}

// single-node transform: node g, channel-pair cp; writes up to 6 outputs to o[]
__device__ __forceinline__ void trans1(
    const LayerSmem* sm, int g, int cp, float* o)
{
    const float* AA = sm->s_A[g];
    if (cp < 16) {
        int c0 = 2 * cp, c1 = c0 + 1;
        float p0 = 0.f, p1 = 0.f;
#pragma unroll
        for (int a = 0; a < 32; a++) {
            float u = sm->s_w1[a * 32 + c0], v = sm->s_w1[a * 32 + c1];
            float x = AA[a];
            p0 = fmaf(x, u, p0); p1 = fmaf(x, v, p1);
        }
#pragma unroll
        for (int a = 0; a < 16; a++) {
            float u = sm->s_w2[a * 32 + c0], v = sm->s_w2[a * 32 + c1];
#pragma unroll
            for (int k = 0; k < 3; k++) {
                float t = AA[80 + 80 * k + 32 + 3 * a + k];
                p0 = fmaf(t, u, p0); p1 = fmaf(t, v, p1);
            }
        }
        o[0] = p0; o[1] = p1;
    } else {
        int c0 = 2 * (cp - 16), c1 = c0 + 1;
        float r[6] = {0, 0, 0, 0, 0, 0};
#pragma unroll
        for (int a = 0; a < 32; a++) {
            float u = sm->s_w3[a * 16 + c0], v = sm->s_w3[a * 16 + c1];
#pragma unroll
            for (int k = 0; k < 3; k++) {
                float t = AA[80 + 80 * k + a];
                r[k] = fmaf(t, u, r[k]); r[3 + k] = fmaf(t, v, r[3 + k]);
            }
        }
#pragma unroll
        for (int a = 0; a < 16; a++) {
            float u = sm->s_w4[a * 16 + c0], v = sm->s_w4[a * 16 + c1];
#pragma unroll
            for (int k = 0; k < 3; k++) {
                float t = AA[32 + 3 * a + k];
                r[k] = fmaf(t, u, r[k]); r[3 + k] = fmaf(t, v, r[3 + k]);
            }
        }
#pragma unroll
        for (int i = 0; i < 6; i++) o[i] = r[i];
    }
}

__global__ __launch_bounds__(256) void k_layer(
    const ulonglong2* __restrict__ hq, const int* __restrict__ rowptr,
    const int* __restrict__ csrc, const uint2* __restrict__ coefh,
    const float* __restrict__ w1, const float* __restrict__ w2,
    const float* __restrict__ w3, const float* __restrict__ w4,
    float* __restrict__ hout)
{
    __shared__ LayerSmem sm;
    int tid = threadIdx.x, wid = tid >> 5, lane = tid & 31;
    int nb = blockIdx.x * 8;
    stage_w(&sm, tid, 256, w1, w2, w3, w4);
    layer_agg(&sm, hq, rowptr, csrc, coefh, wid, lane, nb + wid);
    __syncthreads();
    if (tid < 192) {
        int g = tid / 24, cp = tid % 24;
        float o[6];
        trans1(&sm, g, cp, o);
        float* hn = hout + (nb + g) * HID;
        if (cp < 16) {
            hn[2 * cp] = o[0]; hn[2 * cp + 1] = o[1];
        } else {
            int m = cp - 16;
#pragma unroll
            for (int i = 0; i < 6; i++) hn[32 + 6 * m + i] = o[i];
        }
    }
}

__global__ __launch_bounds__(256) void k_layer_final(
    const ulonglong2* __restrict__ hq, const int* __restrict__ rowptr,
    const int* __restrict__ csrc, const uint2* __restrict__ coefh,
    const float* __restrict__ w1, const float* __restrict__ w2,
    const float* __restrict__ w3, const float* __restrict__ w4,
    const float* __restrict__ W_out, const float* __restrict__ b_out,
    float* __restrict__ out)
{
    __shared__ LayerSmem sm;
    __shared__ float s_o[8][HID];
    __shared__ float s_Wo[HID * 8];
    int tid = threadIdx.x, wid = tid >> 5, lane = tid & 31;
    int nb = blockIdx.x * 8;
    stage_w(&sm, tid, 256, w1, w2, w3, w4);
    for (int i = tid; i < HID * 8; i += 256) s_Wo[i] = W_out[i];
    layer_agg(&sm, hq, rowptr, csrc, coefh, wid, lane, nb + wid);
    __syncthreads();
    if (tid < 192) {
        int g = tid / 24, cp = tid % 24;
        float o[6];
        trans1(&sm, g, cp, o);
        if (cp < 16) {
            s_o[g][2 * cp]     = fmaxf(o[0], 0.f);
            s_o[g][2 * cp + 1] = fmaxf(o[1], 0.f);
        } else {
            int m = cp - 16;
#pragma unroll
            for (int i = 0; i < 6; i++) s_o[g][32 + 6 * m + i] = fmaxf(o[i], 0.f);
        }
    }
    __syncthreads();
    if (tid < 64) {
        int node = tid / 8, o = tid % 8;
        float acc = b_out[o];
        const float* so = s_o[node];
#pragma unroll
        for (int c = 0; c < HID; c++)
            acc = fmaf(so[c], s_Wo[c * 8 + o], acc);
        out[(nb + node) * 8 + o] = acc;
    }
}

// ---------------- launch ----------------
extern "C" void kernel_launch(void* const* d_in, const int* in_sizes, int n_in,
                              void* d_out, int out_size) {
    const float* x     = (const float*)d_in[0];
    const int*   eidx  = (const int*)d_in[1];     // (2, E) int32: row0=src, row1=dst
    const float* eattr = (const float*)d_in[2];   // (E, 4)
    const float* W_in  = (const float*)d_in[3];
    const float* b_in  = (const float*)d_in[4];
    const float* tpw1  = (const float*)d_in[5];   // (3,32,32)
    const float* tpw2  = (const float*)d_in[6];   // (3,16,32)
    const float* tpw3  = (const float*)d_in[7];   // (3,32,16)
    const float* tpw4  = (const float*)d_in[8];   // (3,16,16)
    const float* W_out = (const float*)d_in[9];
    const float* b_out = (const float*)d_in[10];
    float* out = (float*)d_out;

    float *h0, *h1; uint2 *coefh; int *deg, *rowptr, *cursor, *csrc;
    cudaGetSymbolAddress((void**)&h0,     g_h0);
    cudaGetSymbolAddress((void**)&h1,     g_h1);
    cudaGetSymbolAddress((void**)&deg,    g_deg);
    cudaGetSymbolAddress((void**)&rowptr, g_rowptr);
    cudaGetSymbolAddress((void**)&cursor, g_cursor);
    cudaGetSymbolAddress((void**)&csrc,   g_csrc);
    cudaGetSymbolAddress((void**)&coefh,  g_coefh);

    const int* src = eidx;
    const int* dst = eidx + N_EDGES;

    // 1: fused hist + input embed
    k_pre<<<N_EDGES / 256 + (N_NODES * HID) / 256, 256>>>(dst, deg, x, W_in, b_in, h0);
    // 2: scan (re-zeros deg for replay)
    k_scan<<<1, 1024>>>(deg, rowptr, cursor);
    // 3: CSR fill
    k_csr<<<N_EDGES / 256, 256>>>(src, dst, (const float4*)eattr, cursor, csrc, coefh);

    // 4: layer 0 (h0 -> h1)   [launch #4 = ncu profile slot]
    k_layer<<<N_NODES / 8, 256>>>((const ulonglong2*)h0, rowptr, csrc, coefh,
        tpw1 + 0 * 32 * 32, tpw2 + 0 * 16 * 32,
        tpw3 + 0 * 32 * 16, tpw4 + 0 * 16 * 16, h1);
    // 5: layer 1 (h1 -> h0)
    k_layer<<<N_NODES / 8, 256>>>((const ulonglong2*)h1, rowptr, csrc, coefh,
        tpw1 + 1 * 32 * 32, tpw2 + 1 * 16 * 32,
        tpw3 + 1 * 32 * 16, tpw4 + 1 * 16 * 16, h0);
    // 6: layer 2 + readout (reads h0)
    k_layer_final<<<N_NODES / 8, 256>>>((const ulonglong2*)h0, rowptr, csrc, coefh,
        tpw1 + 2 * 32 * 32, tpw2 + 2 * 16 * 32,
        tpw3 + 2 * 32 * 16, tpw4 + 2 * 16 * 16, W_out, b_out, out);
}

// round 13
// speedup vs baseline: 1.1586x; 1.1586x over previous
#include <cuda_runtime.h>
#include <cuda_fp16.h>

#define N_NODES 65536
#define N_EDGES 1048576
#define HID 80
#define NPB 16          // nodes per k_layer block
#define SA_STRIDE 324   // floats per node in s_A (2-way max conflicts, float4-aligned)

typedef unsigned long long u64;

// ---------------- static scratch (no allocations allowed) ----------------
__device__ float g_h0[N_NODES * HID];        // h fp32 ping (21 MB)
__device__ float g_h1[N_NODES * HID];        // h fp32 pong (21 MB)
__device__ int   g_deg[N_NODES];             // zero at load; re-zeroed by k_scan each run
__device__ int   g_rowptr[N_NODES + 1];
__device__ int   g_cursor[N_NODES];
__device__ int   g_csrc[N_EDGES];
__device__ uint2 g_coefh[N_EDGES];           // 4 x fp16 coef (8 MB)

// e3nn fan-in norms * 1/sqrt(2) * 1/sqrt(DEG=16)
#define K1C (0.03125f)
#define K2C (0.025515518f)
#define K3C (0.03125f)
#define K4C (0.044194174f)

__device__ __forceinline__ unsigned int h2u(float a, float b) {
    __half2 h = __floats2half2_rn(a, b);
    return *(const unsigned int*)&h;
}
__device__ __forceinline__ uint2 pack4h(float a, float b, float c, float d) {
    uint2 r; r.x = h2u(a, b); r.y = h2u(c, d); return r;
}
__device__ __forceinline__ float4 unpack4h(uint2 p) {
    float2 lo = __half22float2(*(const __half2*)&p.x);
    float2 hi = __half22float2(*(const __half2*)&p.y);
    return make_float4(lo.x, lo.y, hi.x, hi.y);
}
__device__ __forceinline__ u64 packf2(float a, float b) {
    u64 r; asm("mov.b64 %0, {%1, %2};" : "=l"(r) : "f"(a), "f"(b)); return r;
}
__device__ __forceinline__ float2 unpackf2(u64 v) {
    float2 f; asm("mov.b64 {%0, %1}, %2;" : "=f"(f.x), "=f"(f.y) : "l"(v)); return f;
}
__device__ __forceinline__ void ffma2(u64& acc, u64 a, u64 b) {
    asm("fma.rn.f32x2 %0, %1, %2, %0;" : "+l"(acc) : "l"(a), "l"(b));
}

// ---------------- fused preprocessing: hist + input embed ----------------
__global__ void k_pre(const int* __restrict__ dst, int* __restrict__ deg,
                      const float* __restrict__ x, const float* __restrict__ W_in,
                      const float* __restrict__ b_in, float* __restrict__ h) {
    int b = blockIdx.x;
    if (b < N_EDGES / 256) {
        int e = b * 256 + threadIdx.x;
        atomicAdd(&deg[dst[e]], 1);
    } else {
        int id = (b - N_EDGES / 256) * 256 + threadIdx.x;   // < N*80
        int n = id / HID, c = id % HID;
        const float* xr = x + n * 16;
        float acc = b_in[c];
#pragma unroll
        for (int i = 0; i < 16; i++) acc = fmaf(xr[i], W_in[i * HID + c], acc);
        h[id] = acc;
    }
}

// single-block (1024 threads) exclusive scan over 65536 ints; re-zeroes deg (replay-safe)
__global__ __launch_bounds__(1024) void k_scan(
    int* __restrict__ deg, int* __restrict__ rowptr, int* __restrict__ cursor)
{
    __shared__ int wsum[32];
    int tid = threadIdx.x;
    int lane = tid & 31, wid = tid >> 5;
    int base = tid * 64;
    const int4* d4 = (const int4*)(deg + base);
    int s = 0;
#pragma unroll
    for (int i = 0; i < 16; i++) {
        int4 v = d4[i];
        s += v.x + v.y + v.z + v.w;
    }
    int v = s;
#pragma unroll
    for (int d = 1; d < 32; d <<= 1) {
        int t = __shfl_up_sync(0xffffffffu, v, d);
        if (lane >= d) v += t;
    }
    if (lane == 31) wsum[wid] = v;
    __syncthreads();
    if (wid == 0) {
        int w = wsum[lane];
        int wv = w;
#pragma unroll
        for (int d = 1; d < 32; d <<= 1) {
            int t = __shfl_up_sync(0xffffffffu, wv, d);
            if (lane >= d) wv += t;
        }
        wsum[lane] = wv - w;
    }
    __syncthreads();
    int off = wsum[wid] + (v - s);
#pragma unroll 4
    for (int i = 0; i < 16; i++) {
        int4 dv = d4[i];
        int b = base + 4 * i;
        rowptr[b + 0] = off; cursor[b + 0] = off; off += dv.x;
        rowptr[b + 1] = off; cursor[b + 1] = off; off += dv.y;
        rowptr[b + 2] = off; cursor[b + 2] = off; off += dv.z;
        rowptr[b + 3] = off; cursor[b + 3] = off; off += dv.w;
    }
    int4* d4w = (int4*)(deg + base);
    int4 z = make_int4(0, 0, 0, 0);
#pragma unroll 4
    for (int i = 0; i < 16; i++) d4w[i] = z;
    if (tid == 1023) rowptr[N_NODES] = off;
}

__global__ void k_csr(const int* __restrict__ src, const int* __restrict__ dst,
                      const float4* __restrict__ eattr,
                      int* __restrict__ cursor, int* __restrict__ csrc,
                      uint2* __restrict__ coefh) {
    int e = blockIdx.x * blockDim.x + threadIdx.x;
    if (e >= N_EDGES) return;
    int d = dst[e];
    int pos = atomicAdd(&cursor[d], 1);
    csrc[pos] = src[e];
    float4 cf = eattr[e];
    coefh[pos] = pack4h(cf.x, cf.y, cf.z, cf.w);   // (s2, v2x, v2y, v2z)
}

// ================= fused layer: 16 nodes/block (512 thr), agg + 2-node trans =====
// Reads hin, writes hout — DISJOINT buffers (ping-pong): no cross-block races.

struct LayerSmem {
    float  s_w1[1024], s_w2[512], s_w3[512], s_w4[256];   // 9.2 KB, prescaled
    float  s_A[NPB * SA_STRIDE];                          // 20.7 KB fp32 aggregates
    float4 s_cf[NPB][32];                                 // 8 KB coef (unduplicated)
    int    s_src[NPB][32];                                // 2 KB
};

__device__ __forceinline__ void stage_w(
    LayerSmem* sm, int tid, int nth,
    const float* __restrict__ w1, const float* __restrict__ w2,
    const float* __restrict__ w3, const float* __restrict__ w4)
{
    for (int i = tid; i < 1024; i += nth) sm->s_w1[i] = K1C * w1[i];
    for (int i = tid; i < 512;  i += nth) sm->s_w2[i] = K2C * w2[i];
    for (int i = tid; i < 512;  i += nth) sm->s_w3[i] = K3C * w3[i];
    for (int i = tid; i < 256;  i += nth) sm->s_w4[i] = K4C * w4[i];
}

__device__ __forceinline__ void layer_agg(
    LayerSmem* sm, const ulonglong2* __restrict__ hq,
    const int* __restrict__ rowptr, const int* __restrict__ csrc,
    const uint2* __restrict__ coefh, int wid, int lane, int n)
{
    int beg = rowptr[n], end = rowptr[n + 1];
    u64 a0 = 0, a1 = 0, b0 = 0, b1 = 0, c0 = 0, c1 = 0, d0 = 0, d1 = 0;
    for (int base = beg; base < end; base += 32) {
        int cnt = min(32, end - base);
        __syncwarp();
        if (lane < cnt) {
            sm->s_src[wid][lane] = csrc[base + lane];
            sm->s_cf[wid][lane]  = unpack4h(coefh[base + lane]);
        }
        __syncwarp();
        if (lane < 20) {
#pragma unroll 4
            for (int i = 0; i < cnt; i++) {
                int s = sm->s_src[wid][i];
                float4 cf = sm->s_cf[wid][i];          // LDS.128 broadcast
                ulonglong2 f = hq[s * 20 + lane];      // LDG.128: 4 fp32, pre-paired
                u64 cx = packf2(cf.x, cf.x);
                u64 cy = packf2(cf.y, cf.y);
                u64 cz = packf2(cf.z, cf.z);
                u64 cw = packf2(cf.w, cf.w);
                ffma2(a0, cx, f.x); ffma2(a1, cx, f.y);
                ffma2(b0, cy, f.x); ffma2(b1, cy, f.y);
                ffma2(c0, cz, f.x); ffma2(c1, cz, f.y);
                ffma2(d0, cw, f.x); ffma2(d1, cw, f.y);
            }
        }
    }
    if (lane < 20) {
        float* An = sm->s_A + wid * SA_STRIDE;
        float2 p, q;
        p = unpackf2(a0); q = unpackf2(a1);
        *(float4*)&An[0   + 4 * lane] = make_float4(p.x, p.y, q.x, q.y);
        p = unpackf2(b0); q = unpackf2(b1);
        *(float4*)&An[80  + 4 * lane] = make_float4(p.x, p.y, q.x, q.y);
        p = unpackf2(c0); q = unpackf2(c1);
        *(float4*)&An[160 + 4 * lane] = make_float4(p.x, p.y, q.x, q.y);
        p = unpackf2(d0); q = unpackf2(d1);
        *(float4*)&An[240 + 4 * lane] = make_float4(p.x, p.y, q.x, q.y);
    }
}

// 2-node x 2-channel transform: thread (g = node pair 0..7, cp = channel pair 0..23)
__device__ __forceinline__ void trans2(
    const LayerSmem* sm, int g, int cp, float* oA, float* oB)
{
    const float* AA = sm->s_A + (2 * g) * SA_STRIDE;
    const float* AB = AA + SA_STRIDE;
    if (cp < 16) {
        int c0 = 2 * cp, c1 = c0 + 1;
        float pA0 = 0.f, pA1 = 0.f, pB0 = 0.f, pB1 = 0.f;
#pragma unroll
        for (int a = 0; a < 32; a++) {
            float u = sm->s_w1[a * 32 + c0], v = sm->s_w1[a * 32 + c1];
            float xA = AA[a], xB = AB[a];
            pA0 = fmaf(xA, u, pA0); pA1 = fmaf(xA, v, pA1);
            pB0 = fmaf(xB, u, pB0); pB1 = fmaf(xB, v, pB1);
        }
#pragma unroll
        for (int a = 0; a < 16; a++) {
            float u = sm->s_w2[a * 32 + c0], v = sm->s_w2[a * 32 + c1];
#pragma unroll
            for (int k = 0; k < 3; k++) {
                float tA = AA[80 + 80 * k + 32 + 3 * a + k];
                float tB = AB[80 + 80 * k + 32 + 3 * a + k];
                pA0 = fmaf(tA, u, pA0); pA1 = fmaf(tA, v, pA1);
                pB0 = fmaf(tB, u, pB0); pB1 = fmaf(tB, v, pB1);
            }
        }
        oA[0] = pA0; oA[1] = pA1; oB[0] = pB0; oB[1] = pB1;
    } else {
        int c0 = 2 * (cp - 16), c1 = c0 + 1;
        float rA[6] = {0,0,0,0,0,0}, rB[6] = {0,0,0,0,0,0};
#pragma unroll
        for (int a = 0; a < 32; a++) {
            float u = sm->s_w3[a * 16 + c0], v = sm->s_w3[a * 16 + c1];
#pragma unroll
            for (int k = 0; k < 3; k++) {
                float tA = AA[80 + 80 * k + a];
                float tB = AB[80 + 80 * k + a];
                rA[k]     = fmaf(tA, u, rA[k]);     rA[3 + k] = fmaf(tA, v, rA[3 + k]);
                rB[k]     = fmaf(tB, u, rB[k]);     rB[3 + k] = fmaf(tB, v, rB[3 + k]);
            }
        }
#pragma unroll
        for (int a = 0; a < 16; a++) {
            float u = sm->s_w4[a * 16 + c0], v = sm->s_w4[a * 16 + c1];
#pragma unroll
            for (int k = 0; k < 3; k++) {
                float tA = AA[32 + 3 * a + k];
                float tB = AB[32 + 3 * a + k];
                rA[k]     = fmaf(tA, u, rA[k]);     rA[3 + k] = fmaf(tA, v, rA[3 + k]);
                rB[k]     = fmaf(tB, u, rB[k]);     rB[3 + k] = fmaf(tB, v, rB[3 + k]);
            }
        }
#pragma unroll
        for (int i = 0; i < 6; i++) { oA[i] = rA[i]; oB[i] = rB[i]; }
    }
}

__global__ __launch_bounds__(512) void k_layer(
    const ulonglong2* __restrict__ hq, const int* __restrict__ rowptr,
    const int* __restrict__ csrc, const uint2* __restrict__ coefh,
    const float* __restrict__ w1, const float* __restrict__ w2,
    const float* __restrict__ w3, const float* __restrict__ w4,
    float* __restrict__ hout)
{
    __shared__ LayerSmem sm;
    int tid = threadIdx.x, wid = tid >> 5, lane = tid & 31;
    int nb = blockIdx.x * NPB;
    stage_w(&sm, tid, 512, w1, w2, w3, w4);
    layer_agg(&sm, hq, rowptr, csrc, coefh, wid, lane, nb + wid);
    __syncthreads();
    if (tid < 192) {
        int g = tid / 24, cp = tid % 24;
        float oA[6], oB[6];
        trans2(&sm, g, cp, oA, oB);
        float* hA = hout + (nb + 2 * g) * HID;
        float* hB = hA + HID;
        if (cp < 16) {
            int c0 = 2 * cp;
            hA[c0] = oA[0]; hA[c0 + 1] = oA[1];
            hB[c0] = oB[0]; hB[c0 + 1] = oB[1];
        } else {
            int m = cp - 16;   // channels 2m,2m+1 -> h[32+6m .. 32+6m+5]
#pragma unroll
            for (int i = 0; i < 6; i++) {
                hA[32 + 6 * m + i] = oA[i];
                hB[32 + 6 * m + i] = oB[i];
            }
        }
    }
}

__global__ __launch_bounds__(512) void k_layer_final(
    const ulonglong2* __restrict__ hq, const int* __restrict__ rowptr,
    const int* __restrict__ csrc, const uint2* __restrict__ coefh,
    const float* __restrict__ w1, const float* __restrict__ w2,
    const float* __restrict__ w3, const float* __restrict__ w4,
    const float* __restrict__ W_out, const float* __restrict__ b_out,
    float* __restrict__ out)
{
    __shared__ LayerSmem sm;
    __shared__ float s_o[NPB][HID];
    int tid = threadIdx.x, wid = tid >> 5, lane = tid & 31;
    int nb = blockIdx.x * NPB;
    stage_w(&sm, tid, 512, w1, w2, w3, w4);
    layer_agg(&sm, hq, rowptr, csrc, coefh, wid, lane, nb + wid);
    __syncthreads();
    if (tid < 192) {
        int g = tid / 24, cp = tid % 24;
        float oA[6], oB[6];
        trans2(&sm, g, cp, oA, oB);
        int nA = 2 * g, nB = nA + 1;
        if (cp < 16) {
            int c0 = 2 * cp;
            s_o[nA][c0]     = fmaxf(oA[0], 0.f);
            s_o[nA][c0 + 1] = fmaxf(oA[1], 0.f);
            s_o[nB][c0]     = fmaxf(oB[0], 0.f);
            s_o[nB][c0 + 1] = fmaxf(oB[1], 0.f);
        } else {
            int m = cp - 16;
#pragma unroll
            for (int i = 0; i < 6; i++) {
                s_o[nA][32 + 6 * m + i] = fmaxf(oA[i], 0.f);
                s_o[nB][32 + 6 * m + i] = fmaxf(oB[i], 0.f);
            }
        }
    }
    __syncthreads();
    if (tid < NPB * 8) {
        int node = tid / 8, o = tid % 8;
        float acc = b_out[o];
        const float* so = s_o[node];
#pragma unroll
        for (int c = 0; c < HID; c++)
            acc = fmaf(so[c], W_out[c * 8 + o], acc);
        out[(nb + node) * 8 + o] = acc;
    }
}

// ---------------- launch ----------------
extern "C" void kernel_launch(void* const* d_in, const int* in_sizes, int n_in,
                              void* d_out, int out_size) {
    const float* x     = (const float*)d_in[0];
    const int*   eidx  = (const int*)d_in[1];     // (2, E) int32: row0=src, row1=dst
    const float* eattr = (const float*)d_in[2];   // (E, 4)
    const float* W_in  = (const float*)d_in[3];
    const float* b_in  = (const float*)d_in[4];
    const float* tpw1  = (const float*)d_in[5];   // (3,32,32)
    const float* tpw2  = (const float*)d_in[6];   // (3,16,32)
    const float* tpw3  = (const float*)d_in[7];   // (3,32,16)
    const float* tpw4  = (const float*)d_in[8];   // (3,16,16)
    const float* W_out = (const float*)d_in[9];
    const float* b_out = (const float*)d_in[10];
    float* out = (float*)d_out;

    float *h0, *h1; uint2 *coefh; int *deg, *rowptr, *cursor, *csrc;
    cudaGetSymbolAddress((void**)&h0,     g_h0);
    cudaGetSymbolAddress((void**)&h1,     g_h1);
    cudaGetSymbolAddress((void**)&deg,    g_deg);
    cudaGetSymbolAddress((void**)&rowptr, g_rowptr);
    cudaGetSymbolAddress((void**)&cursor, g_cursor);
    cudaGetSymbolAddress((void**)&csrc,   g_csrc);
    cudaGetSymbolAddress((void**)&coefh,  g_coefh);

    const int* src = eidx;
    const int* dst = eidx + N_EDGES;

    // 1: fused hist + input embed
    k_pre<<<N_EDGES / 256 + (N_NODES * HID) / 256, 256>>>(dst, deg, x, W_in, b_in, h0);
    // 2: scan (re-zeros deg for replay)
    k_scan<<<1, 1024>>>(deg, rowptr, cursor);
    // 3: CSR fill
    k_csr<<<N_EDGES / 256, 256>>>(src, dst, (const float4*)eattr, cursor, csrc, coefh);

    // 4: layer 0 (h0 -> h1)   [launch #4 = ncu profile slot]
    k_layer<<<N_NODES / NPB, 512>>>((const ulonglong2*)h0, rowptr, csrc, coefh,
        tpw1 + 0 * 32 * 32, tpw2 + 0 * 16 * 32,
        tpw3 + 0 * 32 * 16, tpw4 + 0 * 16 * 16, h1);
    // 5: layer 1 (h1 -> h0)
    k_layer<<<N_NODES / NPB, 512>>>((const ulonglong2*)h1, rowptr, csrc, coefh,
        tpw1 + 1 * 32 * 32, tpw2 + 1 * 16 * 32,
        tpw3 + 1 * 32 * 16, tpw4 + 1 * 16 * 16, h0);
    // 6: layer 2 + readout (reads h0)
    k_layer_final<<<N_NODES / NPB, 512>>>((const ulonglong2*)h0, rowptr, csrc, coefh,
        tpw1 + 2 * 32 * 32, tpw2 + 2 * 16 * 32,
        tpw3 + 2 * 32 * 16, tpw4 + 2 * 16 * 16, W_out, b_out, out);
}